// round 5
// baseline (speedup 1.0000x reference)
#include <cuda_runtime.h>
#include <cstdint>

#define TTOK 8192
#define HDIM 2048
#define EDIM 8
#define IDIM 1408
#define TWOI 2816
#define NSLOT (TTOK*2)

// ---------------- scratch (static device allocations only) ----------------
__device__ int8_t g_xq[(size_t)TTOK*HDIM];      // quantized activations
__device__ float  g_xs[TTOK];                    // per-token act scale
__device__ float  g_gates[TTOK*2];               // top-2 renormalized gates
__device__ int    g_cnt[EDIM];                   // per-expert routed count
__device__ int    g_tok[EDIM*TTOK];              // per-expert token list
__device__ int    g_slotl[EDIM*TTOK];            // per-expert slot list (t*2+k)
__device__ float  g_afp[(size_t)NSLOT*IDIM];     // SwiGLU output fp32
__device__ int8_t g_aq[(size_t)NSLOT*IDIM];      // requantized intermediate
__device__ float  g_as[NSLOT];                   // intermediate scale
__device__ float  g_y[(size_t)NSLOT*HDIM];       // fc2 output per slot

// ---------------------------------------------------------------------------
__global__ void k_zero() {
    if (threadIdx.x < EDIM) g_cnt[threadIdx.x] = 0;
}

// ------------- gating + dynamic int8 quant + routing (8 tokens/block) ------
__global__ void k_gate(const float* __restrict__ x, const float* __restrict__ gw) {
    __shared__ float s_red[8][9];
    __shared__ float s_scale;
    const int tid  = threadIdx.x;
    const int lane = tid & 31;
    const int wid  = tid >> 5;

    for (int tt = 0; tt < 8; ++tt) {
        const int t = blockIdx.x * 8 + tt;
        const float4* xp = reinterpret_cast<const float4*>(x + (size_t)t * HDIM) + tid * 2;
        float4 x0 = xp[0], x1 = xp[1];

        float am = 0.0f;
        am = fmaxf(am, fabsf(x0.x)); am = fmaxf(am, fabsf(x0.y));
        am = fmaxf(am, fabsf(x0.z)); am = fmaxf(am, fabsf(x0.w));
        am = fmaxf(am, fabsf(x1.x)); am = fmaxf(am, fabsf(x1.y));
        am = fmaxf(am, fabsf(x1.z)); am = fmaxf(am, fabsf(x1.w));

        float acc[8];
        #pragma unroll
        for (int e = 0; e < 8; ++e) {
            const float4* gp = reinterpret_cast<const float4*>(gw + (size_t)e * HDIM) + tid * 2;
            float4 g0 = gp[0], g1 = gp[1];
            acc[e] = x0.x*g0.x + x0.y*g0.y + x0.z*g0.z + x0.w*g0.w
                   + x1.x*g1.x + x1.y*g1.y + x1.z*g1.z + x1.w*g1.w;
        }
        #pragma unroll
        for (int off = 16; off; off >>= 1) {
            #pragma unroll
            for (int e = 0; e < 8; ++e)
                acc[e] += __shfl_xor_sync(0xffffffffu, acc[e], off);
            am = fmaxf(am, __shfl_xor_sync(0xffffffffu, am, off));
        }
        __syncthreads();              // protect s_red from previous token
        if (lane == 0) {
            #pragma unroll
            for (int e = 0; e < 8; ++e) s_red[wid][e] = acc[e];
            s_red[wid][8] = am;
        }
        __syncthreads();
        if (tid == 0) {
            float lg[8];
            float amax = 0.0f;
            #pragma unroll
            for (int e = 0; e < 8; ++e) {
                float s = 0.0f;
                #pragma unroll
                for (int w = 0; w < 8; ++w) s += s_red[w][e];
                lg[e] = s;
            }
            #pragma unroll
            for (int w = 0; w < 8; ++w) amax = fmaxf(amax, s_red[w][8]);

            float mx = lg[0];
            #pragma unroll
            for (int e = 1; e < 8; ++e) mx = fmaxf(mx, lg[e]);
            float p[8];
            #pragma unroll
            for (int e = 0; e < 8; ++e) p[e] = expf(lg[e] - mx);

            int b0 = 0; float v0 = p[0];
            #pragma unroll
            for (int e = 1; e < 8; ++e) if (p[e] > v0) { v0 = p[e]; b0 = e; }
            int b1 = -1; float v1 = -1.0f;
            #pragma unroll
            for (int e = 0; e < 8; ++e) if (e != b0 && p[e] > v1) { v1 = p[e]; b1 = e; }

            float inv = 1.0f / (v0 + v1);
            g_gates[t*2]   = v0 * inv;
            g_gates[t*2+1] = v1 * inv;

            float sc = fmaxf(amax / 127.0f, 1e-8f);
            g_xs[t] = sc;
            s_scale = sc;

            int q0 = atomicAdd(&g_cnt[b0], 1);
            g_tok[b0*TTOK + q0]   = t;
            g_slotl[b0*TTOK + q0] = t*2;
            int q1 = atomicAdd(&g_cnt[b1], 1);
            g_tok[b1*TTOK + q1]   = t;
            g_slotl[b1*TTOK + q1] = t*2 + 1;
        }
        __syncthreads();
        const float sc = s_scale;
        int q[8];
        q[0] = (int)fmaxf(fminf(rintf(x0.x/sc), 127.f), -127.f);
        q[1] = (int)fmaxf(fminf(rintf(x0.y/sc), 127.f), -127.f);
        q[2] = (int)fmaxf(fminf(rintf(x0.z/sc), 127.f), -127.f);
        q[3] = (int)fmaxf(fminf(rintf(x0.w/sc), 127.f), -127.f);
        q[4] = (int)fmaxf(fminf(rintf(x1.x/sc), 127.f), -127.f);
        q[5] = (int)fmaxf(fminf(rintf(x1.y/sc), 127.f), -127.f);
        q[6] = (int)fmaxf(fminf(rintf(x1.z/sc), 127.f), -127.f);
        q[7] = (int)fmaxf(fminf(rintf(x1.w/sc), 127.f), -127.f);
        unsigned lo = (q[0]&255) | ((q[1]&255)<<8) | ((q[2]&255)<<16) | (((unsigned)q[3])<<24);
        unsigned hi = (q[4]&255) | ((q[5]&255)<<8) | ((q[6]&255)<<16) | (((unsigned)q[7])<<24);
        reinterpret_cast<uint2*>(g_xq + (size_t)t * HDIM)[tid] = make_uint2(lo, hi);
    }
}

// ------------------------- int8 tensor-core MMA ----------------------------
__device__ __forceinline__ void mma_s8(int* c, const unsigned* a, const unsigned* b) {
    asm volatile(
        "mma.sync.aligned.m16n8k32.row.col.s32.s8.s8.s32 "
        "{%0,%1,%2,%3}, {%4,%5,%6,%7}, {%8,%9}, {%0,%1,%2,%3};"
        : "+r"(c[0]), "+r"(c[1]), "+r"(c[2]), "+r"(c[3])
        : "r"(a[0]), "r"(a[1]), "r"(a[2]), "r"(a[3]), "r"(b[0]), "r"(b[1]));
}

// Grouped w8a8 GEMM.  CTA tile 256(M) x 128(N) x 64(K), 512 threads.
// MODE 0 (fc1): A = g_xq gathered by token, B rows interleave gate/up pairs,
//               epilogue = dequant + SwiGLU -> g_afp[slot][IDIM]
// MODE 1 (fc2): A = g_aq gathered by slot, epilogue = dequant -> g_y[slot][HDIM]
template <int MODE>
__global__ void __launch_bounds__(512, 1)
k_gemm(const int* __restrict__ W, const float* __restrict__ cs) {
    constexpr int K = (MODE == 0) ? HDIM : IDIM;
    const int e  = blockIdx.z;
    const int cnt = g_cnt[e];
    const int m0 = blockIdx.y * 256;
    if (m0 >= cnt) return;
    const int tid = threadIdx.x;

    __shared__ __align__(16) int8_t As[256 * 80];
    __shared__ __align__(16) int8_t Bs[128 * 80];
    __shared__ int   s_arow[256];
    __shared__ int   s_orow[256];
    __shared__ float s_rs[256];

    if (tid < 256) {
        int r = min(m0 + tid, cnt - 1);
        int ar = (MODE == 0) ? g_tok[e*TTOK + r] : g_slotl[e*TTOK + r];
        s_arow[tid] = ar;
        s_orow[tid] = g_slotl[e*TTOK + r];
        s_rs[tid]   = (MODE == 0) ? g_xs[ar] : g_as[ar];
    }
    __syncthreads();

    const int arow = tid >> 1, ahalf = tid & 1;     // A: 256 rows, 32B halves
    const int brow = tid >> 2, bq    = tid & 3;     // B: 128 rows, 16-int quarters

    const int8_t* Ag = (MODE == 0) ? g_xq : g_aq;
    const size_t abase = (size_t)s_arow[arow] * K + ahalf * 32;
    size_t wbase;
    if (MODE == 0) {
        const int n0p = blockIdx.x * 64;
        wbase = ((size_t)e * TWOI + (size_t)((brow & 1) * IDIM) + n0p + (brow >> 1)) * (size_t)K;
    } else {
        const int n0 = blockIdx.x * 128;
        wbase = ((size_t)e * HDIM + n0 + brow) * (size_t)K;
    }

    const int lane = tid & 31;
    const int wid  = tid >> 5;
    const int wm   = (wid & 7) * 32;
    const int wn   = (wid >> 3) * 64;
    const int gidr = lane >> 2, tig = lane & 3;

    int c[2][8][4];
    #pragma unroll
    for (int mi = 0; mi < 2; ++mi)
        #pragma unroll
        for (int nj = 0; nj < 8; ++nj)
            #pragma unroll
            for (int r = 0; r < 4; ++r) c[mi][nj][r] = 0;

    #pragma unroll 1
    for (int k0 = 0; k0 < K; k0 += 64) {
        int4 av0 = *reinterpret_cast<const int4*>(Ag + abase + k0);
        int4 av1 = *reinterpret_cast<const int4*>(Ag + abase + k0 + 16);
        const int* wg = W + wbase + k0 + bq * 16;
        unsigned pk[4];
        #pragma unroll
        for (int v = 0; v < 4; ++v) {
            int4 w = *reinterpret_cast<const int4*>(wg + v * 4);
            pk[v] = (w.x & 255) | ((w.y & 255) << 8) | ((w.z & 255) << 16) | (((unsigned)w.w) << 24);
        }
        __syncthreads();
        *reinterpret_cast<int4*>(As + arow * 80 + ahalf * 32)      = av0;
        *reinterpret_cast<int4*>(As + arow * 80 + ahalf * 32 + 16) = av1;
        *reinterpret_cast<uint4*>(Bs + brow * 80 + bq * 16) = make_uint4(pk[0], pk[1], pk[2], pk[3]);
        __syncthreads();

        #pragma unroll
        for (int kk = 0; kk < 64; kk += 32) {
            unsigned af[2][4], bf[8][2];
            #pragma unroll
            for (int mi = 0; mi < 2; ++mi) {
                const int8_t* p = As + (wm + mi * 16 + gidr) * 80 + kk + tig * 4;
                af[mi][0] = *reinterpret_cast<const unsigned*>(p);
                af[mi][1] = *reinterpret_cast<const unsigned*>(p + 8 * 80);
                af[mi][2] = *reinterpret_cast<const unsigned*>(p + 16);
                af[mi][3] = *reinterpret_cast<const unsigned*>(p + 8 * 80 + 16);
            }
            #pragma unroll
            for (int nj = 0; nj < 8; ++nj) {
                const int8_t* q = Bs + (wn + nj * 8 + gidr) * 80 + kk + tig * 4;
                bf[nj][0] = *reinterpret_cast<const unsigned*>(q);
                bf[nj][1] = *reinterpret_cast<const unsigned*>(q + 16);
            }
            #pragma unroll
            for (int mi = 0; mi < 2; ++mi)
                #pragma unroll
                for (int nj = 0; nj < 8; ++nj)
                    mma_s8(c[mi][nj], af[mi], bf[nj]);
        }
    }

    // ---------------- epilogue ----------------
    #pragma unroll
    for (int mi = 0; mi < 2; ++mi) {
        #pragma unroll
        for (int h2 = 0; h2 < 2; ++h2) {
            const int rloc = wm + mi * 16 + gidr + h2 * 8;
            if (m0 + rloc >= cnt) continue;
            const float rsv = s_rs[rloc];
            const int orow  = s_orow[rloc];
            #pragma unroll
            for (int nj = 0; nj < 8; ++nj) {
                if (MODE == 0) {
                    const int pcol = blockIdx.x * 64 + (wn >> 1) + nj * 4 + tig;
                    const float csg = cs[(size_t)e * TWOI + pcol];
                    const float csu = cs[(size_t)e * TWOI + IDIM + pcol];
                    const float g = (float)c[mi][nj][h2 * 2 + 0] * rsv * csg;
                    const float u = (float)c[mi][nj][h2 * 2 + 1] * rsv * csu;
                    const float a = (g / (1.0f + expf(-g))) * u;
                    g_afp[(size_t)orow * IDIM + pcol] = a;
                } else {
                    const int col = blockIdx.x * 128 + wn + nj * 8 + tig * 2;
                    const float v0 = (float)c[mi][nj][h2 * 2 + 0] * rsv * cs[(size_t)e * HDIM + col];
                    const float v1 = (float)c[mi][nj][h2 * 2 + 1] * rsv * cs[(size_t)e * HDIM + col + 1];
                    g_y[(size_t)orow * HDIM + col]     = v0;
                    g_y[(size_t)orow * HDIM + col + 1] = v1;
                }
            }
        }
    }
}

// --------------- per-slot dynamic requant of SwiGLU output -----------------
__global__ void k_requant() {
    __shared__ float s_warp[8];
    __shared__ float s_sc;
    const int slot = blockIdx.x;
    const int tid  = threadIdx.x;
    const int lane = tid & 31, wid = tid >> 5;
    const float* ap = g_afp + (size_t)slot * IDIM;

    const bool has2 = tid < (IDIM / 4 - 256);   // 352 float4 per row
    float4 v0 = reinterpret_cast<const float4*>(ap)[tid];
    float4 v1 = make_float4(0.f, 0.f, 0.f, 0.f);
    if (has2) v1 = reinterpret_cast<const float4*>(ap)[tid + 256];

    float am = 0.0f;
    am = fmaxf(am, fabsf(v0.x)); am = fmaxf(am, fabsf(v0.y));
    am = fmaxf(am, fabsf(v0.z)); am = fmaxf(am, fabsf(v0.w));
    am = fmaxf(am, fabsf(v1.x)); am = fmaxf(am, fabsf(v1.y));
    am = fmaxf(am, fabsf(v1.z)); am = fmaxf(am, fabsf(v1.w));
    #pragma unroll
    for (int off = 16; off; off >>= 1)
        am = fmaxf(am, __shfl_xor_sync(0xffffffffu, am, off));
    if (lane == 0) s_warp[wid] = am;
    __syncthreads();
    if (tid == 0) {
        float mm = 0.0f;
        #pragma unroll
        for (int w = 0; w < 8; ++w) mm = fmaxf(mm, s_warp[w]);
        float sc = fmaxf(mm / 127.0f, 1e-8f);
        g_as[slot] = sc;
        s_sc = sc;
    }
    __syncthreads();
    const float sc = s_sc;

    int q0 = (int)fmaxf(fminf(rintf(v0.x/sc), 127.f), -127.f);
    int q1 = (int)fmaxf(fminf(rintf(v0.y/sc), 127.f), -127.f);
    int q2 = (int)fmaxf(fminf(rintf(v0.z/sc), 127.f), -127.f);
    int q3 = (int)fmaxf(fminf(rintf(v0.w/sc), 127.f), -127.f);
    unsigned* qp = reinterpret_cast<unsigned*>(g_aq + (size_t)slot * IDIM);
    qp[tid] = (q0&255) | ((q1&255)<<8) | ((q2&255)<<16) | (((unsigned)q3)<<24);
    if (has2) {
        q0 = (int)fmaxf(fminf(rintf(v1.x/sc), 127.f), -127.f);
        q1 = (int)fmaxf(fminf(rintf(v1.y/sc), 127.f), -127.f);
        q2 = (int)fmaxf(fminf(rintf(v1.z/sc), 127.f), -127.f);
        q3 = (int)fmaxf(fminf(rintf(v1.w/sc), 127.f), -127.f);
        qp[tid + 256] = (q0&255) | ((q1&255)<<8) | ((q2&255)<<16) | (((unsigned)q3)<<24);
    }
}

// ----------------- combine: shared residual + gated experts ----------------
__global__ void k_combine(const float* __restrict__ sh, float* __restrict__ out) {
    const int t   = blockIdx.x;
    const int tid = threadIdx.x;
    const float g0 = g_gates[t*2];
    const float g1 = g_gates[t*2 + 1];
    const float4* y0 = reinterpret_cast<const float4*>(g_y + (size_t)(t*2) * HDIM);
    const float4* y1 = reinterpret_cast<const float4*>(g_y + (size_t)(t*2 + 1) * HDIM);
    const float4* s4 = reinterpret_cast<const float4*>(sh + (size_t)t * HDIM);
    float4* o4 = reinterpret_cast<float4*>(out + (size_t)t * HDIM);
    #pragma unroll
    for (int i = tid; i < HDIM / 4; i += 256) {
        float4 a = s4[i], b = y0[i], c = y1[i];
        float4 r;
        r.x = a.x + g0 * b.x + g1 * c.x;
        r.y = a.y + g0 * b.y + g1 * c.y;
        r.z = a.z + g0 * b.z + g1 * c.z;
        r.w = a.w + g0 * b.w + g1 * c.w;
        o4[i] = r;
    }
}

// ---------------------------------------------------------------------------
extern "C" void kernel_launch(void* const* d_in, const int* in_sizes, int n_in,
                              void* d_out, int out_size) {
    const float* x    = (const float*)d_in[0];   // [4,2048,2048]
    const float* gw   = (const float*)d_in[1];   // [8,2048]
    const int*   w13  = (const int*)  d_in[2];   // [8,2816,2048]
    const float* s13  = (const float*)d_in[3];   // [8,2816]
    const int*   w2   = (const int*)  d_in[4];   // [8,2048,1408]
    const float* s2   = (const float*)d_in[5];   // [8,2048]
    const float* sh   = (const float*)d_in[6];   // [8192,2048]
    float* out = (float*)d_out;

    k_zero<<<1, 32>>>();
    k_gate<<<TTOK / 8, 256>>>(x, gw);
    k_gemm<0><<<dim3(IDIM / 64, 32, EDIM), 512>>>(w13, s13);
    k_requant<<<NSLOT, 256>>>();
    k_gemm<1><<<dim3(HDIM / 128, 32, EDIM), 512>>>(w2, s2);
    k_combine<<<TTOK, 256>>>(sh, out);
}

// round 7
// speedup vs baseline: 1.0455x; 1.0455x over previous
#include <cuda_runtime.h>
#include <cstdint>

#define TTOK 8192
#define HDIM 2048
#define EDIM 8
#define IDIM 1408
#define TWOI 2816
#define NSLOT (TTOK*2)

// ---------------- scratch (static device allocations only) ----------------
__device__ int8_t g_xq[(size_t)TTOK*HDIM];      // quantized activations
__device__ float  g_xs[TTOK];                    // per-token act scale
__device__ float  g_gates[TTOK*2];               // top-2 renormalized gates
__device__ int    g_cnt[EDIM];                   // per-expert routed count
__device__ int    g_tok[EDIM*TTOK];              // per-expert token list
__device__ int    g_slotl[EDIM*TTOK];            // per-expert slot list (t*2+k)
__device__ float  g_afp[(size_t)NSLOT*IDIM];     // SwiGLU output fp32
__device__ int8_t g_aq[(size_t)NSLOT*IDIM];      // requantized intermediate
__device__ float  g_as[NSLOT];                   // intermediate scale
__device__ float  g_y[(size_t)NSLOT*HDIM];       // fc2 output per slot
__device__ int8_t g_w13p[(size_t)EDIM*TWOI*HDIM]; // packed int8 w13
__device__ int8_t g_w2p[(size_t)EDIM*HDIM*IDIM];  // packed int8 w2

// ---------------------------------------------------------------------------
__global__ void k_zero() {
    if (threadIdx.x < EDIM) g_cnt[threadIdx.x] = 0;
}

// ------------------- weight prepack: int32 -> int8 -------------------------
__global__ void k_pack13(const int4* __restrict__ w) {
    unsigned* p = reinterpret_cast<unsigned*>(g_w13p);
    const int n4 = (EDIM * TWOI * HDIM) / 4;
    for (int i = blockIdx.x * blockDim.x + threadIdx.x; i < n4; i += gridDim.x * blockDim.x) {
        int4 v = w[i];
        p[i] = (v.x & 255) | ((v.y & 255) << 8) | ((v.z & 255) << 16) | (((unsigned)v.w) << 24);
    }
}
__global__ void k_pack2(const int4* __restrict__ w) {
    unsigned* p = reinterpret_cast<unsigned*>(g_w2p);
    const int n4 = (EDIM * HDIM * IDIM) / 4;
    for (int i = blockIdx.x * blockDim.x + threadIdx.x; i < n4; i += gridDim.x * blockDim.x) {
        int4 v = w[i];
        p[i] = (v.x & 255) | ((v.y & 255) << 8) | ((v.z & 255) << 16) | (((unsigned)v.w) << 24);
    }
}

// ------------- gating + dynamic int8 quant + routing (8 tokens/block) ------
__global__ void k_gate(const float* __restrict__ x, const float* __restrict__ gw) {
    __shared__ float s_red[8][9];
    __shared__ float s_scale;
    const int tid  = threadIdx.x;
    const int lane = tid & 31;
    const int wid  = tid >> 5;

    for (int tt = 0; tt < 8; ++tt) {
        const int t = blockIdx.x * 8 + tt;
        const float4* xp = reinterpret_cast<const float4*>(x + (size_t)t * HDIM) + tid * 2;
        float4 x0 = xp[0], x1 = xp[1];

        float am = 0.0f;
        am = fmaxf(am, fabsf(x0.x)); am = fmaxf(am, fabsf(x0.y));
        am = fmaxf(am, fabsf(x0.z)); am = fmaxf(am, fabsf(x0.w));
        am = fmaxf(am, fabsf(x1.x)); am = fmaxf(am, fabsf(x1.y));
        am = fmaxf(am, fabsf(x1.z)); am = fmaxf(am, fabsf(x1.w));

        float acc[8];
        #pragma unroll
        for (int e = 0; e < 8; ++e) {
            const float4* gp = reinterpret_cast<const float4*>(gw + (size_t)e * HDIM) + tid * 2;
            float4 g0 = gp[0], g1 = gp[1];
            acc[e] = x0.x*g0.x + x0.y*g0.y + x0.z*g0.z + x0.w*g0.w
                   + x1.x*g1.x + x1.y*g1.y + x1.z*g1.z + x1.w*g1.w;
        }
        #pragma unroll
        for (int off = 16; off; off >>= 1) {
            #pragma unroll
            for (int e = 0; e < 8; ++e)
                acc[e] += __shfl_xor_sync(0xffffffffu, acc[e], off);
            am = fmaxf(am, __shfl_xor_sync(0xffffffffu, am, off));
        }
        __syncthreads();
        if (lane == 0) {
            #pragma unroll
            for (int e = 0; e < 8; ++e) s_red[wid][e] = acc[e];
            s_red[wid][8] = am;
        }
        __syncthreads();
        if (tid == 0) {
            float lg[8];
            float amax = 0.0f;
            #pragma unroll
            for (int e = 0; e < 8; ++e) {
                float s = 0.0f;
                #pragma unroll
                for (int w = 0; w < 8; ++w) s += s_red[w][e];
                lg[e] = s;
            }
            #pragma unroll
            for (int w = 0; w < 8; ++w) amax = fmaxf(amax, s_red[w][8]);

            float mx = lg[0];
            #pragma unroll
            for (int e = 1; e < 8; ++e) mx = fmaxf(mx, lg[e]);
            float p[8];
            #pragma unroll
            for (int e = 0; e < 8; ++e) p[e] = expf(lg[e] - mx);

            int b0 = 0; float v0 = p[0];
            #pragma unroll
            for (int e = 1; e < 8; ++e) if (p[e] > v0) { v0 = p[e]; b0 = e; }
            int b1 = -1; float v1 = -1.0f;
            #pragma unroll
            for (int e = 0; e < 8; ++e) if (e != b0 && p[e] > v1) { v1 = p[e]; b1 = e; }

            float inv = 1.0f / (v0 + v1);
            g_gates[t*2]   = v0 * inv;
            g_gates[t*2+1] = v1 * inv;

            float sc = fmaxf(amax / 127.0f, 1e-8f);
            g_xs[t] = sc;
            s_scale = sc;

            int q0 = atomicAdd(&g_cnt[b0], 1);
            g_tok[b0*TTOK + q0]   = t;
            g_slotl[b0*TTOK + q0] = t*2;
            int q1 = atomicAdd(&g_cnt[b1], 1);
            g_tok[b1*TTOK + q1]   = t;
            g_slotl[b1*TTOK + q1] = t*2 + 1;
        }
        __syncthreads();
        const float sc = s_scale;
        int q[8];
        q[0] = (int)fmaxf(fminf(rintf(x0.x/sc), 127.f), -127.f);
        q[1] = (int)fmaxf(fminf(rintf(x0.y/sc), 127.f), -127.f);
        q[2] = (int)fmaxf(fminf(rintf(x0.z/sc), 127.f), -127.f);
        q[3] = (int)fmaxf(fminf(rintf(x0.w/sc), 127.f), -127.f);
        q[4] = (int)fmaxf(fminf(rintf(x1.x/sc), 127.f), -127.f);
        q[5] = (int)fmaxf(fminf(rintf(x1.y/sc), 127.f), -127.f);
        q[6] = (int)fmaxf(fminf(rintf(x1.z/sc), 127.f), -127.f);
        q[7] = (int)fmaxf(fminf(rintf(x1.w/sc), 127.f), -127.f);
        unsigned lo = (q[0]&255) | ((q[1]&255)<<8) | ((q[2]&255)<<16) | (((unsigned)q[3])<<24);
        unsigned hi = (q[4]&255) | ((q[5]&255)<<8) | ((q[6]&255)<<16) | (((unsigned)q[7])<<24);
        reinterpret_cast<uint2*>(g_xq + (size_t)t * HDIM)[tid] = make_uint2(lo, hi);
    }
}

// ------------------------- int8 tensor-core MMA ----------------------------
__device__ __forceinline__ void mma_s8(int* c, const unsigned* a, const unsigned* b) {
    asm volatile(
        "mma.sync.aligned.m16n8k32.row.col.s32.s8.s8.s32 "
        "{%0,%1,%2,%3}, {%4,%5,%6,%7}, {%8,%9}, {%0,%1,%2,%3};"
        : "+r"(c[0]), "+r"(c[1]), "+r"(c[2]), "+r"(c[3])
        : "r"(a[0]), "r"(a[1]), "r"(a[2]), "r"(a[3]), "r"(b[0]), "r"(b[1]));
}

__device__ __forceinline__ void ldsm_x4(unsigned& r0, unsigned& r1, unsigned& r2, unsigned& r3,
                                        uint32_t addr) {
    asm volatile("ldmatrix.sync.aligned.m8n8.x4.shared.b16 {%0,%1,%2,%3}, [%4];"
                 : "=r"(r0), "=r"(r1), "=r"(r2), "=r"(r3) : "r"(addr));
}

#define CP16(dst, src) \
    asm volatile("cp.async.cg.shared.global [%0], [%1], 16;" :: "r"(dst), "l"(src))

// smem geometry: rows padded to 144B (16B-aligned; stride 144 -> conflict-free
// LDSM phases: 144r mod 128 hits distinct 16B chunks for r=0..7)
#define ASTRIDE 144
#define A_BYTES (256 * ASTRIDE)     // 36864
#define B_BYTES (128 * ASTRIDE)     // 18432
#define STAGE_BYTES (A_BYTES + B_BYTES)
#define NSTAGE 3
#define SMEM_DYN (STAGE_BYTES * NSTAGE)   // 165888

// Grouped w8a8 GEMM.  CTA tile 256(M) x 128(N) x 128(K), 512 threads,
// 3-stage cp.async pipeline, ldmatrix fragment loads, packed int8 weights.
template <int MODE>
__global__ void __launch_bounds__(512, 1)
k_gemm(const float* __restrict__ cs) {
    constexpr int K = (MODE == 0) ? HDIM : IDIM;
    constexpr int KTILES = K / 128;
    const int e   = blockIdx.z;
    const int cnt = g_cnt[e];
    const int m0  = blockIdx.y * 256;
    if (m0 >= cnt) return;
    const int tid = threadIdx.x;

    extern __shared__ __align__(16) int8_t smem[];
    __shared__ int   s_arow[256];
    __shared__ int   s_orow[256];
    __shared__ float s_rs[256];

    if (tid < 256) {
        int r = min(m0 + tid, cnt - 1);
        int ar = (MODE == 0) ? g_tok[e*TTOK + r] : g_slotl[e*TTOK + r];
        s_arow[tid] = ar;
        s_orow[tid] = g_slotl[e*TTOK + r];
        s_rs[tid]   = (MODE == 0) ? g_xs[ar] : g_as[ar];
    }
    __syncthreads();

    const uint32_t smem_u32 = (uint32_t)__cvta_generic_to_shared(smem);

    // ---- per-thread load geometry ----
    // A: 256 rows x 128B; thread -> row tid>>1, 64B half (tid&1), 4x16B chunks
    const int8_t* Ag = (MODE == 0) ? g_xq : g_aq;
    const int8_t* agsrc = Ag + (size_t)s_arow[tid >> 1] * K + (tid & 1) * 64;
    const uint32_t awoff = (uint32_t)((tid >> 1) * ASTRIDE + (tid & 1) * 64);
    // B: 128 rows x 128B; thread -> row tid>>2, 32B quarter (tid&3), 2x16B
    const int brow = tid >> 2;
    size_t wrow;
    if (MODE == 0) {
        const int n0p = blockIdx.x * 64;    // interleaved gate/up pairs
        wrow = (size_t)e * TWOI + (size_t)((brow & 1) * IDIM) + n0p + (brow >> 1);
    } else {
        wrow = (size_t)e * HDIM + blockIdx.x * 128 + brow;
    }
    const int8_t* Wp = (MODE == 0) ? g_w13p : g_w2p;
    const int8_t* bgsrc = Wp + wrow * (size_t)K + (tid & 3) * 32;
    const uint32_t bwoff = (uint32_t)(A_BYTES + brow * ASTRIDE + (tid & 3) * 32);

    // ---- warp/fragment geometry ----
    const int lane = tid & 31;
    const int wid  = tid >> 5;
    const int wm   = (wid & 7) * 32;
    const int wn   = (wid >> 3) * 64;
    const int gidr = lane >> 2, tig = lane & 3;

    // ldmatrix lane->address constants
    const uint32_t a_ld = (uint32_t)((wm + (lane & 15)) * ASTRIDE + (lane >> 4) * 16);
    const uint32_t b_ld = (uint32_t)(A_BYTES
                        + (wn + ((lane >> 4) & 1) * 8 + (lane & 7)) * ASTRIDE
                        + ((lane >> 3) & 1) * 16);

    int c[2][8][4];
    #pragma unroll
    for (int mi = 0; mi < 2; ++mi)
        #pragma unroll
        for (int nj = 0; nj < 8; ++nj)
            #pragma unroll
            for (int r = 0; r < 4; ++r) c[mi][nj][r] = 0;

    // ---- prologue: load stages 0,1 ----
    #pragma unroll
    for (int s = 0; s < 2; ++s) {
        const uint32_t aw = smem_u32 + s * STAGE_BYTES + awoff;
        const int8_t* as = agsrc + s * 128;
        CP16(aw, as); CP16(aw + 16, as + 16); CP16(aw + 32, as + 32); CP16(aw + 48, as + 48);
        const uint32_t bw = smem_u32 + s * STAGE_BYTES + bwoff;
        const int8_t* bs = bgsrc + s * 128;
        CP16(bw, bs); CP16(bw + 16, bs + 16);
        asm volatile("cp.async.commit_group;" ::: "memory");
    }

    #pragma unroll 1
    for (int kt = 0; kt < KTILES; ++kt) {
        asm volatile("cp.async.wait_group 1;" ::: "memory");
        __syncthreads();

        // issue next tile into stage (kt+2)%3 (data of kt-1, consumed + synced)
        if (kt + 2 < KTILES) {
            const int s = (kt + 2) % NSTAGE;
            const uint32_t aw = smem_u32 + s * STAGE_BYTES + awoff;
            const int8_t* as = agsrc + (kt + 2) * 128;
            CP16(aw, as); CP16(aw + 16, as + 16); CP16(aw + 32, as + 32); CP16(aw + 48, as + 48);
            const uint32_t bw = smem_u32 + s * STAGE_BYTES + bwoff;
            const int8_t* bs = bgsrc + (kt + 2) * 128;
            CP16(bw, bs); CP16(bw + 16, bs + 16);
        }
        asm volatile("cp.async.commit_group;" ::: "memory");

        const uint32_t base = smem_u32 + (kt % NSTAGE) * STAGE_BYTES;
        #pragma unroll
        for (int kk = 0; kk < 128; kk += 32) {
            unsigned af[2][4], bf[8][2];
            #pragma unroll
            for (int mi = 0; mi < 2; ++mi)
                ldsm_x4(af[mi][0], af[mi][1], af[mi][2], af[mi][3],
                        base + a_ld + mi * 16 * ASTRIDE + kk);
            #pragma unroll
            for (int njp = 0; njp < 4; ++njp)
                ldsm_x4(bf[2*njp][0], bf[2*njp][1], bf[2*njp+1][0], bf[2*njp+1][1],
                        base + b_ld + njp * 16 * ASTRIDE + kk);
            #pragma unroll
            for (int mi = 0; mi < 2; ++mi)
                #pragma unroll
                for (int nj = 0; nj < 8; ++nj)
                    mma_s8(c[mi][nj], af[mi], bf[nj]);
        }
    }

    // ---------------- epilogue ----------------
    #pragma unroll
    for (int mi = 0; mi < 2; ++mi) {
        #pragma unroll
        for (int h2 = 0; h2 < 2; ++h2) {
            const int rloc = wm + mi * 16 + gidr + h2 * 8;
            if (m0 + rloc >= cnt) continue;
            const float rsv = s_rs[rloc];
            const int orow  = s_orow[rloc];
            #pragma unroll
            for (int nj = 0; nj < 8; ++nj) {
                if (MODE == 0) {
                    const int pcol = blockIdx.x * 64 + (wn >> 1) + nj * 4 + tig;
                    const float csg = cs[(size_t)e * TWOI + pcol];
                    const float csu = cs[(size_t)e * TWOI + IDIM + pcol];
                    const float g = (float)c[mi][nj][h2 * 2 + 0] * rsv * csg;
                    const float u = (float)c[mi][nj][h2 * 2 + 1] * rsv * csu;
                    const float a = (g / (1.0f + expf(-g))) * u;
                    g_afp[(size_t)orow * IDIM + pcol] = a;
                } else {
                    const int col = blockIdx.x * 128 + wn + nj * 8 + tig * 2;
                    const float v0 = (float)c[mi][nj][h2 * 2 + 0] * rsv * cs[(size_t)e * HDIM + col];
                    const float v1 = (float)c[mi][nj][h2 * 2 + 1] * rsv * cs[(size_t)e * HDIM + col + 1];
                    g_y[(size_t)orow * HDIM + col]     = v0;
                    g_y[(size_t)orow * HDIM + col + 1] = v1;
                }
            }
        }
    }
}

// --------------- per-slot dynamic requant of SwiGLU output -----------------
__global__ void k_requant() {
    __shared__ float s_warp[8];
    __shared__ float s_sc;
    const int slot = blockIdx.x;
    const int tid  = threadIdx.x;
    const int lane = tid & 31, wid = tid >> 5;
    const float* ap = g_afp + (size_t)slot * IDIM;

    const bool has2 = tid < (IDIM / 4 - 256);   // 352 float4 per row
    float4 v0 = reinterpret_cast<const float4*>(ap)[tid];
    float4 v1 = make_float4(0.f, 0.f, 0.f, 0.f);
    if (has2) v1 = reinterpret_cast<const float4*>(ap)[tid + 256];

    float am = 0.0f;
    am = fmaxf(am, fabsf(v0.x)); am = fmaxf(am, fabsf(v0.y));
    am = fmaxf(am, fabsf(v0.z)); am = fmaxf(am, fabsf(v0.w));
    am = fmaxf(am, fabsf(v1.x)); am = fmaxf(am, fabsf(v1.y));
    am = fmaxf(am, fabsf(v1.z)); am = fmaxf(am, fabsf(v1.w));
    #pragma unroll
    for (int off = 16; off; off >>= 1)
        am = fmaxf(am, __shfl_xor_sync(0xffffffffu, am, off));
    if (lane == 0) s_warp[wid] = am;
    __syncthreads();
    if (tid == 0) {
        float mm = 0.0f;
        #pragma unroll
        for (int w = 0; w < 8; ++w) mm = fmaxf(mm, s_warp[w]);
        float sc = fmaxf(mm / 127.0f, 1e-8f);
        g_as[slot] = sc;
        s_sc = sc;
    }
    __syncthreads();
    const float sc = s_sc;

    int q0 = (int)fmaxf(fminf(rintf(v0.x/sc), 127.f), -127.f);
    int q1 = (int)fmaxf(fminf(rintf(v0.y/sc), 127.f), -127.f);
    int q2 = (int)fmaxf(fminf(rintf(v0.z/sc), 127.f), -127.f);
    int q3 = (int)fmaxf(fminf(rintf(v0.w/sc), 127.f), -127.f);
    unsigned* qp = reinterpret_cast<unsigned*>(g_aq + (size_t)slot * IDIM);
    qp[tid] = (q0&255) | ((q1&255)<<8) | ((q2&255)<<16) | (((unsigned)q3)<<24);
    if (has2) {
        q0 = (int)fmaxf(fminf(rintf(v1.x/sc), 127.f), -127.f);
        q1 = (int)fmaxf(fminf(rintf(v1.y/sc), 127.f), -127.f);
        q2 = (int)fmaxf(fminf(rintf(v1.z/sc), 127.f), -127.f);
        q3 = (int)fmaxf(fminf(rintf(v1.w/sc), 127.f), -127.f);
        qp[tid + 256] = (q0&255) | ((q1&255)<<8) | ((q2&255)<<16) | (((unsigned)q3)<<24);
    }
}

// ----------------- combine: shared residual + gated experts ----------------
__global__ void k_combine(const float* __restrict__ sh, float* __restrict__ out) {
    const int t   = blockIdx.x;
    const int tid = threadIdx.x;
    const float g0 = g_gates[t*2];
    const float g1 = g_gates[t*2 + 1];
    const float4* y0 = reinterpret_cast<const float4*>(g_y + (size_t)(t*2) * HDIM);
    const float4* y1 = reinterpret_cast<const float4*>(g_y + (size_t)(t*2 + 1) * HDIM);
    const float4* s4 = reinterpret_cast<const float4*>(sh + (size_t)t * HDIM);
    float4* o4 = reinterpret_cast<float4*>(out + (size_t)t * HDIM);
    #pragma unroll
    for (int i = tid; i < HDIM / 4; i += 256) {
        float4 a = s4[i], b = y0[i], c = y1[i];
        float4 r;
        r.x = a.x + g0 * b.x + g1 * c.x;
        r.y = a.y + g0 * b.y + g1 * c.y;
        r.z = a.z + g0 * b.z + g1 * c.z;
        r.w = a.w + g0 * b.w + g1 * c.w;
        o4[i] = r;
    }
}

// ---------------------------------------------------------------------------
extern "C" void kernel_launch(void* const* d_in, const int* in_sizes, int n_in,
                              void* d_out, int out_size) {
    const float* x    = (const float*)d_in[0];   // [4,2048,2048]
    const float* gw   = (const float*)d_in[1];   // [8,2048]
    const int*   w13  = (const int*)  d_in[2];   // [8,2816,2048]
    const float* s13  = (const float*)d_in[3];   // [8,2816]
    const int*   w2   = (const int*)  d_in[4];   // [8,2048,1408]
    const float* s2   = (const float*)d_in[5];   // [8,2048]
    const float* sh   = (const float*)d_in[6];   // [8192,2048]
    float* out = (float*)d_out;

    cudaFuncSetAttribute(k_gemm<0>, cudaFuncAttributeMaxDynamicSharedMemorySize, SMEM_DYN);
    cudaFuncSetAttribute(k_gemm<1>, cudaFuncAttributeMaxDynamicSharedMemorySize, SMEM_DYN);

    k_zero<<<1, 32>>>();
    k_pack13<<<4096, 256>>>((const int4*)w13);
    k_pack2<<<4096, 256>>>((const int4*)w2);
    k_gate<<<TTOK / 8, 256>>>(x, gw);
    k_gemm<0><<<dim3(IDIM / 64, 32, EDIM), 512, SMEM_DYN>>>(s13);
    k_requant<<<NSLOT, 256>>>();
    k_gemm<1><<<dim3(HDIM / 128, 32, EDIM), 512, SMEM_DYN>>>(s2);
    k_combine<<<TTOK, 256>>>(sh, out);
}